// round 6
// baseline (speedup 1.0000x reference)
#include <cuda_runtime.h>
#include <cstdint>
#include <cstddef>

// ---------------------------------------------------------------------------
// Persistent grouped-RNN, round 3 design (resubmit #3 after broker timeouts).
//   16 groups x 32 batch rows; 8 CTAs/group x 64 output cols; 128 CTAs.
//   128 threads/CTA = 4 warps: (2 N-halves) x (2 K-halves), warp tile 32x32.
//   mma.sync m16n8k8 tf32; fragments loaded as float4 from a K-permuted smem
//   layout (4 k-chunks per LDS.128).
//   relu(state) is written tf32 + pre-permuted to a double-buffered __device__
//   scratch by the epilogue -> staging is a raw float4 copy (no cvt/relu).
// ---------------------------------------------------------------------------

namespace {
constexpr int Bb = 512;
constexpr int Hh = 512;
constexpr int Ii = 13;
constexpr int GROUPS = 16;
constexpr int CPG = 8;
constexpr int MT = 32;          // rows per group
constexpr int NT = 64;          // cols per CTA
constexpr int THREADS = 128;
constexpr int NBLK = 17;        // 17 blocks x 32 perm-cols = 544 K (512 + 13 xin + pad)
constexpr int STR = 560;        // smem row stride (floats); 560 % 32 == 16 -> conflict-free
constexpr int WS_OFF = 0;                  // Ws: 64 x STR
constexpr int AS_OFF = 64 * STR;           // As: 32 x STR
constexpr int NZ_OFF = AS_OFF + 32 * STR;  // Nz: 32 x 72
constexpr int NZ_STR = 72;
constexpr int PX_OFF = AS_OFF;             // K-partials reuse the As region
constexpr int PX_STR = 36;                 // per-lane stride (floats), conflict-free
constexpr int SMEM_FLOATS = NZ_OFF + 32 * NZ_STR;
constexpr int SMEM_BYTES = SMEM_FLOATS * 4;   // 224,256 B
constexpr float LEAK = 0.8f;
constexpr float ALPHA_ = 0.2f;
constexpr float SIGMA_ = 0.15811388300841898f;  // sqrt(2/0.2)*0.05
}

__device__ unsigned g_bar[GROUPS];
// relu(state), tf32, K-permuted, double buffered: [parity][row][perm-col 0..511]
__device__ float g_scr[2][Bb][512];

__device__ __forceinline__ unsigned ld_acq(const unsigned* p) {
    unsigned v;
    asm volatile("ld.acquire.gpu.u32 %0, [%1];" : "=r"(v) : "l"(p));
    return v;
}
__device__ __forceinline__ uint32_t tf32_rna(float x) {
    uint32_t r;
    asm("cvt.rna.tf32.f32 %0, %1;" : "=r"(r) : "f"(x));
    return r;
}
// perm within a 32-col block: k = 32b + 8j + q  ->  32b + 4q + j
__device__ __forceinline__ int permc(int k) {
    return (k & ~31) + ((k & 7) << 2) + ((k >> 3) & 3);
}
__device__ __forceinline__ void mma_tf32(float c[4], uint32_t a0, uint32_t a1,
                                         uint32_t a2, uint32_t a3,
                                         uint32_t b0, uint32_t b1) {
    asm volatile(
        "mma.sync.aligned.m16n8k8.row.col.f32.tf32.tf32.f32 "
        "{%0,%1,%2,%3},{%4,%5,%6,%7},{%8,%9},{%0,%1,%2,%3};"
        : "+f"(c[0]), "+f"(c[1]), "+f"(c[2]), "+f"(c[3])
        : "r"(a0), "r"(a1), "r"(a2), "r"(a3), "r"(b0), "r"(b1));
}
#define F4C(v, j) ((j) == 0 ? (v).x : (j) == 1 ? (v).y : (j) == 2 ? (v).z : (v).w)

__device__ __forceinline__ void group_barrier(int g, unsigned epoch) {
    __syncthreads();
    if (threadIdx.x == 0) {
        __threadfence();
        atomicAdd(&g_bar[g], 1u);
        const unsigned target = epoch * (unsigned)CPG;
        while (ld_acq(&g_bar[g]) < target) {}
    }
    __syncthreads();
}

__global__ void __launch_bounds__(THREADS, 1)
rnn_kernel(const float* __restrict__ inputs, const float* __restrict__ init,
           const float* __restrict__ noise, const float* __restrict__ wih,
           const float* __restrict__ whh, const float* __restrict__ bias,
           float* __restrict__ out, int T) {
    extern __shared__ float smem[];
    float* Ws = smem + WS_OFF;
    float* As = smem + AS_OFF;
    float* Nz = smem + NZ_OFF;
    float* Px = smem + PX_OFF;

    const int g = blockIdx.x / CPG;
    const int cid = blockIdx.x % CPG;
    const int m0 = g * MT;
    const int n0 = cid * NT;
    const int tid = threadIdx.x;
    const int lane = tid & 31;
    const int w = tid >> 5;
    const int gid = lane >> 2;   // 0..7
    const int qid = lane & 3;    // 0..3
    const int nhalf = w & 1;     // which 32-col half this warp computes
    const int khalf = w >> 1;    // which K half

    // ---- one-time: W' = [whh(diag-masked); wih; 0] -> Ws[n][perm-k], tf32
    for (int idx = tid; idx < NT * (NBLK * 32); idx += THREADS) {
        const int n = idx / (NBLK * 32);
        const int pp = idx % (NBLK * 32);
        const int b = pp >> 5, o = pp & 31, q = o >> 2, j = o & 3;
        const int k = b * 32 + 8 * j + q;
        float v;
        if (k < Hh) {
            v = whh[k * Hh + (n0 + n)];
            if (k == n0 + n) v = 0.f;
        } else if (k - Hh < Ii) {
            v = wih[(k - Hh) * Hh + (n0 + n)];
        } else {
            v = 0.f;
        }
        Ws[n * STR + pp] = __uint_as_float(tf32_rna(v));
    }

    // ---- per-thread static epilogue metadata (warps 0,1 only use it)
    float bia[8];
    int pcol[8];   // permuted scratch col (0..511) for each of this thread's 8 cols
    float prev[2][4][4];
#pragma unroll
    for (int nt = 0; nt < 4; nt++) {
#pragma unroll
        for (int c = 0; c < 2; c++) {
            const int gc = n0 + nhalf * 32 + nt * 8 + 2 * qid + c;
            bia[nt * 2 + c] = bias[gc];
            pcol[nt * 2 + c] = permc(gc);
        }
    }
    if (khalf == 0) {
#pragma unroll
        for (int mt = 0; mt < 2; mt++)
#pragma unroll
            for (int nt = 0; nt < 4; nt++) {
                const int col = n0 + nhalf * 32 + nt * 8 + 2 * qid;
                const size_t r0 = (size_t)(m0 + mt * 16 + gid) * Hh + col;
                float2 v0 = *reinterpret_cast<const float2*>(&init[r0]);
                float2 v1 = *reinterpret_cast<const float2*>(&init[r0 + 8 * Hh]);
                prev[mt][nt][0] = v0.x; prev[mt][nt][1] = v0.y;
                prev[mt][nt][2] = v1.x; prev[mt][nt][3] = v1.y;
            }
    }

    // ---- out[0] = initial_state (this CTA's 32x64 slice)
    for (int i = tid; i < MT * (NT / 4); i += THREADS) {
        const int r = i >> 4, c4 = (i & 15) << 2;
        const size_t off = (size_t)(m0 + r) * Hh + n0 + c4;
        *reinterpret_cast<float4*>(&out[off]) =
            *reinterpret_cast<const float4*>(&init[off]);
    }
    // ---- scratch[0] slice = relu(init), tf32, permuted
    for (int i = tid; i < MT * NT; i += THREADS) {
        const int r = i >> 6, c = i & 63;
        const int gc = n0 + c;
        const float v = fmaxf(init[(size_t)(m0 + r) * Hh + gc], 0.f);
        g_scr[0][m0 + r][permc(gc)] = __uint_as_float(tf32_rna(v));
    }

    group_barrier(g, 1u);

    const int b0 = khalf ? 9 : 0;
    const int b1 = khalf ? NBLK : 9;
    const float* Abase = As + gid * STR + qid * 4;
    const float* Bbase = Ws + (nhalf * 32 + gid) * STR + qid * 4;

    for (int t = 0; t < T; t++) {
        // ---- stage: noise first (DRAM, longest latency in flight earliest)
        for (int i = tid; i < MT * 16; i += THREADS) {           // noise 32x64
            const int r = i >> 4, c4 = (i & 15) << 2;
            *reinterpret_cast<float4*>(&Nz[r * NZ_STR + c4]) =
                *reinterpret_cast<const float4*>(
                    &noise[((size_t)t * Bb + m0 + r) * Hh + n0 + c4]);
        }
        // ---- stage A (raw copy of permuted tf32 scratch, L2-hot)
        const float* src = &g_scr[t & 1][m0][0];
        for (int i = tid; i < MT * 128; i += THREADS) {          // 4096 float4
            const int r = i >> 7, c4 = (i & 127) << 2;
            *reinterpret_cast<float4*>(&As[r * STR + c4]) =
                *reinterpret_cast<const float4*>(&src[r * 512 + c4]);
        }
        for (int i = tid; i < MT * 32; i += THREADS) {           // xin block 16
            const int r = i >> 5, o = i & 31, q = o >> 2, j = o & 3;
            const int kk = 8 * j + q;
            const float v = (kk < Ii)
                ? inputs[((size_t)t * Bb + m0 + r) * Ii + kk] : 0.f;
            As[r * STR + 512 + o] = __uint_as_float(tf32_rna(v));
        }
        __syncthreads();

        // ---- 32x32 warp-tile GEMM over this warp's K half
        float acc[2][4][4] = {};
        for (int b = b0; b < b1; ++b) {
            const int co = b * 32;
            float4 fa[4][2], fb[4][2];
#pragma unroll
            for (int r = 0; r < 4; ++r) {
                fa[r][0] = *reinterpret_cast<const float4*>(Abase + r * 8 * STR + co);
                fa[r][1] = *reinterpret_cast<const float4*>(Abase + r * 8 * STR + co + 16);
                fb[r][0] = *reinterpret_cast<const float4*>(Bbase + r * 8 * STR + co);
                fb[r][1] = *reinterpret_cast<const float4*>(Bbase + r * 8 * STR + co + 16);
            }
#pragma unroll
            for (int j = 0; j < 4; ++j) {
#pragma unroll
                for (int mt = 0; mt < 2; ++mt) {
                    const uint32_t a0 = __float_as_uint(F4C(fa[2 * mt][0], j));
                    const uint32_t a1 = __float_as_uint(F4C(fa[2 * mt + 1][0], j));
                    const uint32_t a2 = __float_as_uint(F4C(fa[2 * mt][1], j));
                    const uint32_t a3 = __float_as_uint(F4C(fa[2 * mt + 1][1], j));
#pragma unroll
                    for (int nt = 0; nt < 4; ++nt)
                        mma_tf32(acc[mt][nt], a0, a1, a2, a3,
                                 __float_as_uint(F4C(fb[nt][0], j)),
                                 __float_as_uint(F4C(fb[nt][1], j)));
                }
            }
        }
        __syncthreads();

        // ---- K-split reduction: warps 2,3 publish partials into (free) As area
        if (khalf == 1) {
            float* p = Px + (nhalf * 32 + lane) * PX_STR;
#pragma unroll
            for (int mt = 0; mt < 2; ++mt)
#pragma unroll
                for (int nt = 0; nt < 4; ++nt)
                    *reinterpret_cast<float4*>(&p[(mt * 4 + nt) * 4]) =
                        make_float4(acc[mt][nt][0], acc[mt][nt][1],
                                    acc[mt][nt][2], acc[mt][nt][3]);
        }
        __syncthreads();

        // ---- epilogue on warps 0,1
        if (khalf == 0) {
            const float* p = Px + (nhalf * 32 + lane) * PX_STR;
            float* o1 = out + (size_t)(t + 1) * Bb * Hh;
            float (*scr)[512] = g_scr[(t + 1) & 1];
#pragma unroll
            for (int mt = 0; mt < 2; ++mt)
#pragma unroll
                for (int nt = 0; nt < 4; ++nt) {
                    const float4 px = *reinterpret_cast<const float4*>(&p[(mt * 4 + nt) * 4]);
                    const int lc = nhalf * 32 + nt * 8 + 2 * qid;   // local col
                    const int r0 = mt * 16 + gid;
                    const float2 nz0 = *reinterpret_cast<const float2*>(&Nz[r0 * NZ_STR + lc]);
                    const float2 nz1 = *reinterpret_cast<const float2*>(&Nz[(r0 + 8) * NZ_STR + lc]);
                    float s0 = acc[mt][nt][0] + px.x;
                    float s1 = acc[mt][nt][1] + px.y;
                    float s2 = acc[mt][nt][2] + px.z;
                    float s3 = acc[mt][nt][3] + px.w;
                    float2 olo, ohi;
                    olo.x = LEAK * prev[mt][nt][0] + ALPHA_ * (s0 + bia[nt * 2] + SIGMA_ * nz0.x);
                    olo.y = LEAK * prev[mt][nt][1] + ALPHA_ * (s1 + bia[nt * 2 + 1] + SIGMA_ * nz0.y);
                    ohi.x = LEAK * prev[mt][nt][2] + ALPHA_ * (s2 + bia[nt * 2] + SIGMA_ * nz1.x);
                    ohi.y = LEAK * prev[mt][nt][3] + ALPHA_ * (s3 + bia[nt * 2 + 1] + SIGMA_ * nz1.y);
                    prev[mt][nt][0] = olo.x; prev[mt][nt][1] = olo.y;
                    prev[mt][nt][2] = ohi.x; prev[mt][nt][3] = ohi.y;
                    const size_t go = (size_t)(m0 + r0) * Hh + n0 + lc;
                    *reinterpret_cast<float2*>(&o1[go]) = olo;
                    *reinterpret_cast<float2*>(&o1[go + 8 * Hh]) = ohi;
                    // relu + tf32 + permuted scratch for next step's A
                    scr[m0 + r0][pcol[nt * 2]] =
                        __uint_as_float(tf32_rna(fmaxf(olo.x, 0.f)));
                    scr[m0 + r0][pcol[nt * 2 + 1]] =
                        __uint_as_float(tf32_rna(fmaxf(olo.y, 0.f)));
                    scr[m0 + r0 + 8][pcol[nt * 2]] =
                        __uint_as_float(tf32_rna(fmaxf(ohi.x, 0.f)));
                    scr[m0 + r0 + 8][pcol[nt * 2 + 1]] =
                        __uint_as_float(tf32_rna(fmaxf(ohi.y, 0.f)));
                }
        }

        if (t + 1 < T) group_barrier(g, (unsigned)(t + 2));
    }
}

extern "C" void kernel_launch(void* const* d_in, const int* in_sizes, int n_in,
                              void* d_out, int out_size) {
    (void)n_in; (void)out_size;
    const float* inputs = (const float*)d_in[0];
    const float* init   = (const float*)d_in[1];
    const float* noise  = (const float*)d_in[2];
    const float* wih    = (const float*)d_in[3];
    const float* whh    = (const float*)d_in[4];
    const float* bias   = (const float*)d_in[5];
    float* out = (float*)d_out;

    const int T = in_sizes[2] / (Bb * Hh);

    void* barp = nullptr;
    cudaGetSymbolAddress(&barp, g_bar);
    cudaMemsetAsync(barp, 0, GROUPS * sizeof(unsigned));

    cudaFuncSetAttribute(rnn_kernel, cudaFuncAttributeMaxDynamicSharedMemorySize,
                         SMEM_BYTES);
    rnn_kernel<<<GROUPS * CPG, THREADS, SMEM_BYTES>>>(inputs, init, noise, wih,
                                                      whh, bias, out, T);
}